// round 16
// baseline (speedup 1.0000x reference)
#include <cuda_runtime.h>

// NCC loss, 9x9 box, zero pad, win_size=81.
// predict/target: [32,1,512,512] f32 -> scalar f32 = 1 - mean(cross^2/(Ivar*Jvar+1e-6))
//
// Adjacent-column f32x2 packing: thread x owns output cols (2x, 2x+1).
// Horizontal taps come straight from global memory as 5 aligned LDG.64 per image
// (L1 serves the 9x vertical re-reads) -> NO shared-memory tap stage, NO barriers
// in the main loop. Vertical 9-window via register rings (I, J, J2) + thread-
// private smem rings (I2, IJ). 288 blocks x 256 threads, 2 blocks/SM, one wave.

typedef unsigned long long u64;

__device__ __forceinline__ u64 pk2(float lo, float hi) {
    u64 r; asm("mov.b64 %0,{%1,%2};" : "=l"(r) : "f"(lo), "f"(hi)); return r;
}
__device__ __forceinline__ void upk2(u64 v, float& lo, float& hi) {
    asm("mov.b64 {%0,%1},%2;" : "=f"(lo), "=f"(hi) : "l"(v));
}
__device__ __forceinline__ u64 add2(u64 a, u64 b) {
    u64 d; asm("add.rn.f32x2 %0,%1,%2;" : "=l"(d) : "l"(a), "l"(b)); return d;
}
__device__ __forceinline__ u64 mul2(u64 a, u64 b) {
    u64 d; asm("mul.rn.f32x2 %0,%1,%2;" : "=l"(d) : "l"(a), "l"(b)); return d;
}
__device__ __forceinline__ u64 fma2(u64 a, u64 b, u64 c) {
    u64 d; asm("fma.rn.f32x2 %0,%1,%2,%3;" : "=l"(d) : "l"(a), "l"(b), "l"(c)); return d;
}
// {a.hi, b.lo} -> packed pair for odd-offset taps
__device__ __forceinline__ u64 mid2(u64 a, u64 b) {
    u64 d;
    asm("{ .reg .b32 al, ah, bl, bh;\n\t"
        "  mov.b64 {al, ah}, %1;\n\t"
        "  mov.b64 {bl, bh}, %2;\n\t"
        "  mov.b64 %0, {ah, bl}; }"
        : "=l"(d) : "l"(a), "l"(b));
    return d;
}

constexpr int W      = 512;
constexpr int H      = 512;
constexpr int HW     = W * H;
constexpr int BATCH  = 32;
constexpr int STRIPS = 9;
constexpr int SROWS  = 57;                  // strips 0..7: 57 rows, strip 8: 56 (masked)
constexpr int NBLK   = BATCH * STRIPS;      // 288
constexpr int TPB    = 256;
constexpr int ITERS  = SROWS + 8;           // 65
constexpr float INV81 = 1.0f / 81.0f;

__device__ float g_partials[NBLK];
__device__ unsigned int g_ticket = 0;

__global__ void __launch_bounds__(TPB, 2)
ncc_main_kernel(const float* __restrict__ gI, const float* __restrict__ gJ,
                float* __restrict__ out) {
    __shared__ u64 s_rI2[9][TPB];           // thread-private ring slots (no sync needed)
    __shared__ u64 s_rIJ[9][TPB];
    __shared__ float s_wsum[TPB / 32];
    __shared__ int s_last;

    const int x     = threadIdx.x;          // owns output cols 2x, 2x+1
    const int bx    = blockIdx.x;
    const int strip = bx % STRIPS;
    const int batch = bx / STRIPS;
    const int y0    = strip * SROWS;
    const int cbase = 2 * x - 4;             // leftmost loaded column (even)

    const float* pI = gI + (size_t)batch * HW;
    const float* pJ = gJ + (size_t)batch * HW;

    const u64 NEG1 = pk2(-1.0f, -1.0f);
    const u64 M81  = pk2(-INV81, -INV81);
    const u64 EPS  = pk2(1e-6f, 1e-6f);

    u64 rI[9], rJ[9], rJ2[9];
#pragma unroll
    for (int k = 0; k < 9; ++k) {
        rI[k] = 0ull; rJ[k] = 0ull; rJ2[k] = 0ull;
        s_rI2[k][x] = 0ull; s_rIJ[k][x] = 0ull;
    }
    u64 VI = 0ull, VJ = 0ull, VI2 = 0ull, VJ2 = 0ull, VIJ = 0ull;
    float acc = 0.0f;

#pragma unroll 1
    for (int m = 0; m < 8; ++m) {
#pragma unroll
        for (int k = 0; k < 9; ++k) {            // ring slot = it mod 9 (static)
            const int it = m * 9 + k;
            if (it >= ITERS) goto reduce;
            const int r  = y0 - 4 + it;
            const bool inRow = (unsigned)r < (unsigned)H;
            const float* rowI = pI + r * W;
            const float* rowJ = pJ + r * W;

            // 5 aligned 8B loads per image: cols cbase .. cbase+9 (pairs fully in/out)
            u64 LI[5], LJ[5];
#pragma unroll
            for (int i = 0; i < 5; ++i) {
                const int c = cbase + 2 * i;
                LI[i] = 0ull; LJ[i] = 0ull;
                if (inRow && (unsigned)c < (unsigned)W) {
                    const float2 a = __ldg((const float2*)(rowI + c));
                    const float2 b = __ldg((const float2*)(rowJ + c));
                    LI[i] = pk2(a.x, a.y);
                    LJ[i] = pk2(b.x, b.y);
                }
            }

            // 9 packed taps: even k -> LI[k/2]; odd k -> {LI[(k-1)/2].hi, LI[(k+1)/2].lo}
            u64 hI, hJ, hI2, hJ2, hIJ;
            {
                const u64 tI = LI[0], tJ = LJ[0];
                hI = tI; hJ = tJ;
                hI2 = mul2(tI, tI); hJ2 = mul2(tJ, tJ); hIJ = mul2(tI, tJ);
            }
#pragma unroll
            for (int t = 1; t < 9; ++t) {
                u64 tI, tJ;
                if (t & 1) { tI = mid2(LI[(t-1)/2], LI[(t+1)/2]);
                             tJ = mid2(LJ[(t-1)/2], LJ[(t+1)/2]); }
                else       { tI = LI[t/2]; tJ = LJ[t/2]; }
                hI  = add2(hI, tI);
                hJ  = add2(hJ, tJ);
                hI2 = fma2(tI, tI, hI2);
                hJ2 = fma2(tJ, tJ, hJ2);
                hIJ = fma2(tI, tJ, hIJ);
            }

            // vertical running 9-window: V += h_new - h_old
            VI  = add2(VI,  hI );  VI  = fma2(rI [k], NEG1, VI );  rI [k] = hI;
            VJ  = add2(VJ,  hJ );  VJ  = fma2(rJ [k], NEG1, VJ );  rJ [k] = hJ;
            VJ2 = add2(VJ2, hJ2);  VJ2 = fma2(rJ2[k], NEG1, VJ2);  rJ2[k] = hJ2;
            {
                const u64 oI2 = s_rI2[k][x];
                VI2 = add2(VI2, hI2);  VI2 = fma2(oI2, NEG1, VI2);  s_rI2[k][x] = hI2;
                const u64 oIJ = s_rIJ[k][x];
                VIJ = add2(VIJ, hIJ);  VIJ = fma2(oIJ, NEG1, VIJ);  s_rIJ[k][x] = hIJ;
            }

            if (it >= 8 && (y0 + it - 8) < H) {   // output row guard (strip 8 tail)
                const u64 tIn   = mul2(VI, M81);
                const u64 tJn   = mul2(VJ, M81);
                const u64 cross = fma2(tIn, VJ, VIJ);
                const u64 Ivar  = fma2(tIn, VI, VI2);
                const u64 Jvar  = fma2(tJn, VJ, VJ2);
                const u64 num   = mul2(cross, cross);
                const u64 den   = fma2(Ivar, Jvar, EPS);
                float n0, n1, d0, d1;
                upk2(num, n0, n1);
                upk2(den, d0, d1);
                acc += __fdividef(n0, d0);
                acc += __fdividef(n1, d1);
            }
        }
    }
reduce:
    // deterministic block reduction (8 warps)
#pragma unroll
    for (int o = 16; o > 0; o >>= 1) acc += __shfl_xor_sync(0xffffffffu, acc, o);
    if ((x & 31) == 0) s_wsum[x >> 5] = acc;
    __syncthreads();
    if (x == 0) {
        float v = 0.f;
#pragma unroll
        for (int w = 0; w < TPB / 32; ++w) v += s_wsum[w];
        g_partials[bx] = v;
        __threadfence();
        unsigned t = atomicAdd(&g_ticket, 1u);
        s_last = (t == (unsigned)(NBLK - 1)) ? 1 : 0;
    }
    __syncthreads();

    // last block: fixed-order final sum (deterministic)
    if (s_last) {
        const volatile float* gp = g_partials;
        float v = gp[x];
        if (x < NBLK - 256) v += gp[256 + x];     // 288 partials over 256 threads
#pragma unroll
        for (int o = 16; o > 0; o >>= 1) v += __shfl_xor_sync(0xffffffffu, v, o);
        if ((x & 31) == 0) s_wsum[x >> 5] = v;
        __syncthreads();
        if (x == 0) {
            float s = 0.f;
#pragma unroll
            for (int w = 0; w < TPB / 32; ++w) s += s_wsum[w];
            out[0] = 1.0f - s * (1.0f / 8388608.0f);   // N = 2^23 exact
            g_ticket = 0;                               // reset for next graph replay
        }
    }
}

extern "C" void kernel_launch(void* const* d_in, const int* in_sizes, int n_in,
                              void* d_out, int out_size) {
    const float* predict = (const float*)d_in[0];
    const float* target  = (const float*)d_in[1];
    ncc_main_kernel<<<NBLK, TPB>>>(predict, target, (float*)d_out);
}

// round 17
// speedup vs baseline: 1.0045x; 1.0045x over previous
#include <cuda_runtime.h>

// NCC loss, 9x9 box, zero pad, win_size=81.
// predict/target: [32,1,512,512] f32 -> scalar f32 = 1 - mean(cross^2/(Ivar*Jvar+1e-6))
//
// Adjacent-column f32x2 packing: thread x owns output cols (2x, 2x+1).
// Horizontal taps come straight from global memory as 5 aligned LDG.64 per image
// (L1 serves the 9x vertical re-reads) -> NO shared-memory tap stage, NO barriers
// in the main loop. Vertical 9-window via register rings (I, J, J2) + thread-
// private smem rings (I2, IJ). 288 blocks x 256 threads, 2 blocks/SM, one wave.

typedef unsigned long long u64;

__device__ __forceinline__ u64 pk2(float lo, float hi) {
    u64 r; asm("mov.b64 %0,{%1,%2};" : "=l"(r) : "f"(lo), "f"(hi)); return r;
}
__device__ __forceinline__ void upk2(u64 v, float& lo, float& hi) {
    asm("mov.b64 {%0,%1},%2;" : "=f"(lo), "=f"(hi) : "l"(v));
}
__device__ __forceinline__ u64 add2(u64 a, u64 b) {
    u64 d; asm("add.rn.f32x2 %0,%1,%2;" : "=l"(d) : "l"(a), "l"(b)); return d;
}
__device__ __forceinline__ u64 mul2(u64 a, u64 b) {
    u64 d; asm("mul.rn.f32x2 %0,%1,%2;" : "=l"(d) : "l"(a), "l"(b)); return d;
}
__device__ __forceinline__ u64 fma2(u64 a, u64 b, u64 c) {
    u64 d; asm("fma.rn.f32x2 %0,%1,%2,%3;" : "=l"(d) : "l"(a), "l"(b), "l"(c)); return d;
}
// {a.hi, b.lo} -> packed pair for odd-offset taps
__device__ __forceinline__ u64 mid2(u64 a, u64 b) {
    u64 d;
    asm("{ .reg .b32 al, ah, bl, bh;\n\t"
        "  mov.b64 {al, ah}, %1;\n\t"
        "  mov.b64 {bl, bh}, %2;\n\t"
        "  mov.b64 %0, {ah, bl}; }"
        : "=l"(d) : "l"(a), "l"(b));
    return d;
}

constexpr int W      = 512;
constexpr int H      = 512;
constexpr int HW     = W * H;
constexpr int BATCH  = 32;
constexpr int STRIPS = 9;
constexpr int SROWS  = 57;                  // strips 0..7: 57 rows, strip 8: 56 (masked)
constexpr int NBLK   = BATCH * STRIPS;      // 288
constexpr int TPB    = 256;
constexpr int ITERS  = SROWS + 8;           // 65
constexpr float INV81 = 1.0f / 81.0f;

__device__ float g_partials[NBLK];
__device__ unsigned int g_ticket = 0;

__global__ void __launch_bounds__(TPB, 2)
ncc_main_kernel(const float* __restrict__ gI, const float* __restrict__ gJ,
                float* __restrict__ out) {
    __shared__ u64 s_rI2[9][TPB];           // thread-private ring slots (no sync needed)
    __shared__ u64 s_rIJ[9][TPB];
    __shared__ float s_wsum[TPB / 32];
    __shared__ int s_last;

    const int x     = threadIdx.x;          // owns output cols 2x, 2x+1
    const int bx    = blockIdx.x;
    const int strip = bx % STRIPS;
    const int batch = bx / STRIPS;
    const int y0    = strip * SROWS;
    const int cbase = 2 * x - 4;             // leftmost loaded column (even)

    const float* pI = gI + (size_t)batch * HW;
    const float* pJ = gJ + (size_t)batch * HW;

    const u64 NEG1 = pk2(-1.0f, -1.0f);
    const u64 M81  = pk2(-INV81, -INV81);
    const u64 EPS  = pk2(1e-6f, 1e-6f);

    u64 rI[9], rJ[9], rJ2[9];
#pragma unroll
    for (int k = 0; k < 9; ++k) {
        rI[k] = 0ull; rJ[k] = 0ull; rJ2[k] = 0ull;
        s_rI2[k][x] = 0ull; s_rIJ[k][x] = 0ull;
    }
    u64 VI = 0ull, VJ = 0ull, VI2 = 0ull, VJ2 = 0ull, VIJ = 0ull;
    float acc = 0.0f;

#pragma unroll 1
    for (int m = 0; m < 8; ++m) {
#pragma unroll
        for (int k = 0; k < 9; ++k) {            // ring slot = it mod 9 (static)
            const int it = m * 9 + k;
            if (it >= ITERS) goto reduce;
            const int r  = y0 - 4 + it;
            const bool inRow = (unsigned)r < (unsigned)H;
            const float* rowI = pI + r * W;
            const float* rowJ = pJ + r * W;

            // 5 aligned 8B loads per image: cols cbase .. cbase+9 (pairs fully in/out)
            u64 LI[5], LJ[5];
#pragma unroll
            for (int i = 0; i < 5; ++i) {
                const int c = cbase + 2 * i;
                LI[i] = 0ull; LJ[i] = 0ull;
                if (inRow && (unsigned)c < (unsigned)W) {
                    const float2 a = __ldg((const float2*)(rowI + c));
                    const float2 b = __ldg((const float2*)(rowJ + c));
                    LI[i] = pk2(a.x, a.y);
                    LJ[i] = pk2(b.x, b.y);
                }
            }

            // 9 packed taps: even k -> LI[k/2]; odd k -> {LI[(k-1)/2].hi, LI[(k+1)/2].lo}
            u64 hI, hJ, hI2, hJ2, hIJ;
            {
                const u64 tI = LI[0], tJ = LJ[0];
                hI = tI; hJ = tJ;
                hI2 = mul2(tI, tI); hJ2 = mul2(tJ, tJ); hIJ = mul2(tI, tJ);
            }
#pragma unroll
            for (int t = 1; t < 9; ++t) {
                u64 tI, tJ;
                if (t & 1) { tI = mid2(LI[(t-1)/2], LI[(t+1)/2]);
                             tJ = mid2(LJ[(t-1)/2], LJ[(t+1)/2]); }
                else       { tI = LI[t/2]; tJ = LJ[t/2]; }
                hI  = add2(hI, tI);
                hJ  = add2(hJ, tJ);
                hI2 = fma2(tI, tI, hI2);
                hJ2 = fma2(tJ, tJ, hJ2);
                hIJ = fma2(tI, tJ, hIJ);
            }

            // vertical running 9-window: V += h_new - h_old
            VI  = add2(VI,  hI );  VI  = fma2(rI [k], NEG1, VI );  rI [k] = hI;
            VJ  = add2(VJ,  hJ );  VJ  = fma2(rJ [k], NEG1, VJ );  rJ [k] = hJ;
            VJ2 = add2(VJ2, hJ2);  VJ2 = fma2(rJ2[k], NEG1, VJ2);  rJ2[k] = hJ2;
            {
                const u64 oI2 = s_rI2[k][x];
                VI2 = add2(VI2, hI2);  VI2 = fma2(oI2, NEG1, VI2);  s_rI2[k][x] = hI2;
                const u64 oIJ = s_rIJ[k][x];
                VIJ = add2(VIJ, hIJ);  VIJ = fma2(oIJ, NEG1, VIJ);  s_rIJ[k][x] = hIJ;
            }

            if (it >= 8 && (y0 + it - 8) < H) {   // output row guard (strip 8 tail)
                const u64 tIn   = mul2(VI, M81);
                const u64 tJn   = mul2(VJ, M81);
                const u64 cross = fma2(tIn, VJ, VIJ);
                const u64 Ivar  = fma2(tIn, VI, VI2);
                const u64 Jvar  = fma2(tJn, VJ, VJ2);
                const u64 num   = mul2(cross, cross);
                const u64 den   = fma2(Ivar, Jvar, EPS);
                float n0, n1, d0, d1;
                upk2(num, n0, n1);
                upk2(den, d0, d1);
                acc += __fdividef(n0, d0);
                acc += __fdividef(n1, d1);
            }
        }
    }
reduce:
    // deterministic block reduction (8 warps)
#pragma unroll
    for (int o = 16; o > 0; o >>= 1) acc += __shfl_xor_sync(0xffffffffu, acc, o);
    if ((x & 31) == 0) s_wsum[x >> 5] = acc;
    __syncthreads();
    if (x == 0) {
        float v = 0.f;
#pragma unroll
        for (int w = 0; w < TPB / 32; ++w) v += s_wsum[w];
        g_partials[bx] = v;
        __threadfence();
        unsigned t = atomicAdd(&g_ticket, 1u);
        s_last = (t == (unsigned)(NBLK - 1)) ? 1 : 0;
    }
    __syncthreads();

    // last block: fixed-order final sum (deterministic)
    if (s_last) {
        const volatile float* gp = g_partials;
        float v = gp[x];
        if (x < NBLK - 256) v += gp[256 + x];     // 288 partials over 256 threads
#pragma unroll
        for (int o = 16; o > 0; o >>= 1) v += __shfl_xor_sync(0xffffffffu, v, o);
        if ((x & 31) == 0) s_wsum[x >> 5] = v;
        __syncthreads();
        if (x == 0) {
            float s = 0.f;
#pragma unroll
            for (int w = 0; w < TPB / 32; ++w) s += s_wsum[w];
            out[0] = 1.0f - s * (1.0f / 8388608.0f);   // N = 2^23 exact
            g_ticket = 0;                               // reset for next graph replay
        }
    }
}

extern "C" void kernel_launch(void* const* d_in, const int* in_sizes, int n_in,
                              void* d_out, int out_size) {
    const float* predict = (const float*)d_in[0];
    const float* target  = (const float*)d_in[1];
    ncc_main_kernel<<<NBLK, TPB>>>(predict, target, (float*)d_out);
}